// round 12
// baseline (speedup 1.0000x reference)
#include <cuda_runtime.h>
#include <cuda_fp16.h>

// BSplineACTF: per-channel cubic B-spline activation, uniform knots.
// x:[16,256,256,32] f32, grid:[12] f32, W:[32,8] f32 -> out f32.
//
// R12 = R11 (best wall 45.6us: fp16 collapsed-cubic table, LDS.64 + 3 FMA,
// 4-way front-batched __ldcs / __stcs, 2368x256, __launch_bounds__(256,8))
// with ONE change: stores interleaved per sub-iteration (compute a -> store a)
// instead of compute-all-then-store-all. Peak live outputs drop 4 float4 -> 1,
// freeing ~12 regs of scheduling slack under the 32-reg occupancy pin so the
// four LDG.128 stay genuinely front-batched.

#define NTHREADS 256
#define NBLOCKS  2368

__global__ __launch_bounds__(NTHREADS, 8) void bspline_actf_kernel(
    const float* __restrict__ x,
    const float* __restrict__ grid,
    const float* __restrict__ W,
    float* __restrict__ out,
    int n)
{
    // [channel][interval] packed cubic coeffs: lo=(c0,c1), hi=(c2,c3) as half2.
    __shared__ uint2 sc[32 * 11];

    const float g0    = grid[0];
    const float g11   = grid[11];
    const float h     = (g11 - g0) * (1.0f / 11.0f);
    const float inv_h = 1.0f / h;

    // ---- one-time per-block coefficient build (352 records) ----
    for (int idx = threadIdx.x; idx < 32 * 11; idx += NTHREADS) {
        int c = idx / 11;
        int j = idx - c * 11;
        const float* Wc = W + c * 8;
        float w0 = (j     >= 0 && j     < 8) ? __ldg(Wc + j)     : 0.0f;
        float w1 = (j - 1 >= 0 && j - 1 < 8) ? __ldg(Wc + j - 1) : 0.0f;
        float w2 = (j - 2 >= 0 && j - 2 < 8) ? __ldg(Wc + j - 2) : 0.0f;
        float w3 = (j - 3 >= 0 && j - 3 < 8) ? __ldg(Wc + j - 3) : 0.0f;
        float c0 = (w1 + 4.0f * w2 + w3) * (1.0f / 6.0f);
        float c1 = (w1 - w3) * 0.5f;
        float c2 = (w1 - 2.0f * w2 + w3) * 0.5f;
        float c3 = (w0 - 3.0f * w1 + 3.0f * w2 - w3) * (1.0f / 6.0f);
        __half2 lo = __floats2half2_rn(c0, c1);
        __half2 hi = __floats2half2_rn(c2, c3);
        uint2 rec;
        rec.x = *reinterpret_cast<unsigned int*>(&lo);
        rec.y = *reinterpret_cast<unsigned int*>(&hi);
        sc[idx] = rec;
    }
    __syncthreads();

    const int gtid   = blockIdx.x * NTHREADS + threadIdx.x;
    const int stride = gridDim.x * NTHREADS;   // in float4 vectors; % 8 == 0
    const int n4     = n >> 2;

    // channel quartet of this thread's vectors is loop-invariant
    const int c0i = (gtid & 7) * 4;
    const uint2* __restrict__ row0 = sc + (c0i + 0) * 11;
    const uint2* __restrict__ row1 = sc + (c0i + 1) * 11;
    const uint2* __restrict__ row2 = sc + (c0i + 2) * 11;
    const uint2* __restrict__ row3 = sc + (c0i + 3) * 11;

    const float4* __restrict__ x4 = (const float4*)x;
    float4* __restrict__ o4       = (float4*)out;

    auto evalspline = [&](float xv, const uint2* __restrict__ rowp) -> float {
        float u  = (xv - g0) * inv_h;
        float jf = floorf(u);
        int   j  = (int)jf;
        float t  = u - jf;
        int   jc = min(max(j, 0), 10);
        uint2 rec = rowp[jc];                 // LDS.64
        __half2 lo = *reinterpret_cast<__half2*>(&rec.x);
        __half2 hi = *reinterpret_cast<__half2*>(&rec.y);
        float2 f01 = __half22float2(lo);
        float2 f23 = __half22float2(hi);
        float r = fmaf(fmaf(fmaf(f23.y, t, f23.x), t, f01.y), t, f01.x);
        return ((unsigned)j < 11u) ? r : 0.0f;
    };

    auto eval_vec = [&](float4 xv) -> float4 {
        float4 ov;
        ov.x = evalspline(xv.x, row0);
        ov.y = evalspline(xv.y, row1);
        ov.z = evalspline(xv.z, row2);
        ov.w = evalspline(xv.w, row3);
        return ov;
    };

    // 4-way unrolled grid-stride loop: loads front-batched, stores interleaved
    // (one live output float4 at a time -> ~12 regs of scheduling slack).
    int v = gtid;
    for (; v + 3 * stride < n4; v += 4 * stride) {
        float4 xa = __ldcs(&x4[v]);
        float4 xb = __ldcs(&x4[v + stride]);
        float4 xc = __ldcs(&x4[v + 2 * stride]);
        float4 xd = __ldcs(&x4[v + 3 * stride]);
        __stcs(&o4[v],              eval_vec(xa));
        __stcs(&o4[v + stride],     eval_vec(xb));
        __stcs(&o4[v + 2 * stride], eval_vec(xc));
        __stcs(&o4[v + 3 * stride], eval_vec(xd));
    }
    for (; v < n4; v += stride) {
        float4 xv = __ldcs(&x4[v]);
        __stcs(&o4[v], eval_vec(xv));
    }

    // scalar tail (n % 4) — not hit for this shape, kept for safety
    for (int e = (n4 << 2) + gtid; e < n; e += stride) {
        int c = e & 31;
        out[e] = evalspline(x[e], sc + c * 11);
    }
}

extern "C" void kernel_launch(void* const* d_in, const int* in_sizes, int n_in,
                              void* d_out, int out_size)
{
    const float* x    = (const float*)d_in[0];
    const float* grid = (const float*)d_in[1];
    const float* W    = (const float*)d_in[2];
    float* out        = (float*)d_out;
    int n = in_sizes[0];

    int n4 = n >> 2;
    int blocks = NBLOCKS;
    int maxBlocks = (n4 + NTHREADS - 1) / NTHREADS;
    if (maxBlocks < 1) maxBlocks = 1;
    if (blocks > maxBlocks) blocks = maxBlocks;

    bspline_actf_kernel<<<blocks, NTHREADS>>>(x, grid, W, out, n);
}